// round 1
// baseline (speedup 1.0000x reference)
#include <cuda_runtime.h>
#include <math.h>

#define NN     50000
#define RR     4
#define DD     5
#define BB     8
#define TT     10
#define E_RECN 1500000
#define E_INN  200000
#define N_INN  17400
#define RNN    (RR * NN)   // 200000

// ------------------------- device scratch (no allocs) -------------------------
__device__ float4        g_total[BB * NN];        // (b, n, 4 receptors) accumulated input
__device__ float         g_v[BB * NN];
__device__ float         g_r[BB * NN];
__device__ float         g_a1[BB * NN];
__device__ float         g_a2[BB * NN];
__device__ float4        g_psc_rise[BB * NN];
__device__ float4        g_psc[BB * NN];
__device__ unsigned char g_zmask[DD * NN];        // circular delay buffer, 8 batch bits per byte
__device__ unsigned char g_xmask[TT * N_INN];     // packed input spikes
__device__ float2        g_ascd[NN];              // exp(-DT * sigmoid(param_k))

// ------------------------------- init kernel ---------------------------------
__global__ void init_kernel(const float* __restrict__ x,
                            const float* __restrict__ bkg_w,
                            const float2* __restrict__ param_k,
                            const float* __restrict__ v0)
{
    int i      = blockIdx.x * blockDim.x + threadIdx.x;
    int stride = gridDim.x * blockDim.x;

    // total = bkg (broadcast over batch)
    const float4* bkg4 = reinterpret_cast<const float4*>(bkg_w);
    for (int j = i; j < BB * NN; j += stride) {
        g_total[j] = bkg4[j % NN];
    }
    // neuron state
    for (int j = i; j < BB * NN; j += stride) {
        g_v[j]  = v0[j];
        g_r[j]  = 0.0f;
        g_a1[j] = 0.0f;
        g_a2[j] = 0.0f;
        g_psc_rise[j] = make_float4(0.f, 0.f, 0.f, 0.f);
        g_psc[j]      = make_float4(0.f, 0.f, 0.f, 0.f);
    }
    // delay buffer
    for (int j = i; j < DD * NN; j += stride) g_zmask[j] = 0;
    // pack x spikes: bit b = x[t, b, s] > 0.5
    for (int j = i; j < TT * N_INN; j += stride) {
        int t = j / N_INN;
        int s = j - t * N_INN;
        unsigned m = 0;
        #pragma unroll
        for (int b = 0; b < BB; b++) {
            if (x[(t * BB + b) * N_INN + s] > 0.5f) m |= (1u << b);
        }
        g_xmask[j] = (unsigned char)m;
    }
    // asc decay = exp(-DT * sigmoid(k)); DT = 1
    for (int j = i; j < NN; j += stride) {
        float2 pk = param_k[j];
        float s0 = 1.0f / (1.0f + expf(-pk.x));
        float s1 = 1.0f / (1.0f + expf(-pk.y));
        g_ascd[j] = make_float2(expf(-s0), expf(-s1));
    }
}

// ------------------------------ scatter kernel -------------------------------
// One thread per edge (recurrent then input). Early-out on spike bitmask; only
// active edges load tgt/w and issue atomics.
__global__ __launch_bounds__(256)
void scatter_kernel(const int*   __restrict__ rec_src,
                    const int*   __restrict__ rec_tgt,
                    const float* __restrict__ w_rec,
                    const int*   __restrict__ in_src,
                    const int*   __restrict__ in_tgt,
                    const float* __restrict__ w_in,
                    int h_read, int t)
{
    int e = blockIdx.x * blockDim.x + threadIdx.x;
    float* tot = reinterpret_cast<float*>(g_total);

    if (e < E_RECN) {
        int src = rec_src[e];
        int d = src / NN;
        int n = src - d * NN;
        int slot = h_read + d;
        if (slot >= DD) slot -= DD;
        unsigned m = g_zmask[slot * NN + n];
        if (m) {
            float w   = w_rec[e];
            int   tgt = rec_tgt[e];
            #pragma unroll
            for (int b = 0; b < BB; b++) {
                if (m & (1u << b)) atomicAdd(&tot[b * RNN + tgt], w);
            }
        }
    } else if (e < E_RECN + E_INN) {
        int k = e - E_RECN;
        int src = in_src[k];
        unsigned m = g_xmask[t * N_INN + src];
        if (m) {
            float w   = w_in[k];
            int   tgt = in_tgt[k];
            #pragma unroll
            for (int b = 0; b < BB; b++) {
                if (m & (1u << b)) atomicAdd(&tot[b * RNN + tgt], w);
            }
        }
    }
}

// ------------------------------ update kernel --------------------------------
// One thread per neuron, loops batches. Also writes total = bkg for next step.
__global__ __launch_bounds__(256)
void update_kernel(const float*  __restrict__ decay,
                   const float*  __restrict__ current_factor,
                   const float*  __restrict__ v_th,
                   const float*  __restrict__ e_l,
                   const float*  __restrict__ v_reset,
                   const float*  __restrict__ t_ref,
                   const float2* __restrict__ asc_amps,
                   const float*  __restrict__ param_g,
                   const float4* __restrict__ syn_decay,
                   const float4* __restrict__ psc_initial,
                   const float4* __restrict__ bkg4,
                   float*        __restrict__ out,
                   int h_read, int h_write, int t)
{
    int n = blockIdx.x * blockDim.x + threadIdx.x;
    if (n >= NN) return;

    const float  dec  = decay[n];
    const float  cf   = current_factor[n];
    const float  vth  = v_th[n];
    const float  el   = e_l[n];
    const float  vre  = v_reset[n];
    const float  tref = t_ref[n];
    const float2 amps = asc_amps[n];
    const float2 ad   = g_ascd[n];
    const float  g    = param_g[n];
    const float4 sd   = syn_decay[n];
    const float4 pi   = psc_initial[n];
    const float4 bk   = bkg4[n];

    const float gel    = g * el;
    const float invden = 1.0f / (vth - el);
    const float rstamp = vre - vth;

    unsigned pm = g_zmask[h_read * NN + n];
    unsigned nm = 0;

    #pragma unroll
    for (int b = 0; b < BB; b++) {
        int bn = b * NN + n;
        float4 total = g_total[b * NN + n];
        float4 pr = g_psc_rise[bn];
        float4 pc = g_psc[bn];
        float  v  = g_v[bn];
        float  r  = g_r[bn];
        float  a1 = g_a1[bn];
        float  a2 = g_a2[bn];
        float  pz = (pm >> b) & 1u ? 1.0f : 0.0f;

        // old-state reads (match reference ordering)
        float input_cur = pc.x + pc.y + pc.z + pc.w;
        float c1   = input_cur + a1 + a2 + gel;
        float newv = dec * v + cf * c1 + pz * rstamp;
        float newr = fmaxf(r + pz * tref - 1.0f, 0.0f);
        float na1  = ad.x * a1 + pz * amps.x;
        float na2  = ad.y * a2 + pz * amps.y;

        float4 npc, npr;
        npc.x = pc.x * sd.x + sd.x * pr.x;
        npc.y = pc.y * sd.y + sd.y * pr.y;
        npc.z = pc.z * sd.z + sd.z * pr.z;
        npc.w = pc.w * sd.w + sd.w * pr.w;
        npr.x = sd.x * pr.x + pi.x * total.x;
        npr.y = sd.y * pr.y + pi.y * total.y;
        npr.z = sd.z * pr.z + pi.z * total.z;
        npr.w = sd.w * pr.w + pi.w * total.w;

        float vsc = (newv - vth) * invden;
        float z = (vsc > 0.0f) ? 1.0f : 0.0f;
        if (newr > 0.0f) z = 0.0f;
        nm |= (z != 0.0f ? 1u : 0u) << b;

        g_v[bn]  = newv;
        g_r[bn]  = newr;
        g_a1[bn] = na1;
        g_a2[bn] = na2;
        g_psc_rise[bn] = npr;
        g_psc[bn]      = npc;
        g_total[b * NN + n] = bk;        // re-init for next step's scatter

        out[(t * BB + b) * NN + n] = z;
    }
    g_zmask[h_write * NN + n] = (unsigned char)nm;
}

// --------------------------------- launcher ----------------------------------
extern "C" void kernel_launch(void* const* d_in, const int* in_sizes, int n_in,
                              void* d_out, int out_size)
{
    const float* x        = (const float*)d_in[0];
    const float* w_rec    = (const float*)d_in[1];
    const int*   rec_src  = (const int*)  d_in[2];
    const int*   rec_tgt  = (const int*)  d_in[3];
    const float* w_in     = (const float*)d_in[4];
    const int*   in_src   = (const int*)  d_in[5];
    const int*   in_tgt   = (const int*)  d_in[6];
    const float* bkg_w    = (const float*)d_in[7];
    const float* decay    = (const float*)d_in[8];
    const float* cf       = (const float*)d_in[9];
    const float* v_th     = (const float*)d_in[10];
    const float* e_l      = (const float*)d_in[11];
    const float* v_reset  = (const float*)d_in[12];
    const float* t_ref    = (const float*)d_in[13];
    const float2* asc_amps = (const float2*)d_in[14];
    const float2* param_k  = (const float2*)d_in[15];
    const float* param_g   = (const float*)d_in[16];
    const float4* syn_decay   = (const float4*)d_in[17];
    const float4* psc_initial = (const float4*)d_in[18];
    const float* v0        = (const float*)d_in[19];
    float* out = (float*)d_out;

    init_kernel<<<1024, 256>>>(x, bkg_w, param_k, v0);

    const int scatter_blocks = (E_RECN + E_INN + 255) / 256;
    const int update_blocks  = (NN + 255) / 256;

    int h = 0;
    for (int t = 0; t < TT; t++) {
        int h_read  = h;
        int h_write = (h + DD - 1) % DD;
        scatter_kernel<<<scatter_blocks, 256>>>(rec_src, rec_tgt, w_rec,
                                                in_src, in_tgt, w_in,
                                                h_read, t);
        update_kernel<<<update_blocks, 256>>>(decay, cf, v_th, e_l, v_reset, t_ref,
                                              asc_amps, param_g, syn_decay, psc_initial,
                                              (const float4*)bkg_w, out,
                                              h_read, h_write, t);
        h = h_write;
    }
}

// round 2
// speedup vs baseline: 1.0135x; 1.0135x over previous
#include <cuda_runtime.h>
#include <math.h>

#define NN     50000
#define RR     4
#define DD     5
#define BB     8
#define TT     10
#define E_RECN 1500000
#define E_INN  200000
#define N_INN  17400
#define RNN    (RR * NN)   // 200000
#define ZLEN   (DD * NN)   // 250000

#define REC_QUADS (E_RECN / 4)             // 375000
#define IN_QUADS  (E_INN / 4)              // 50000
#define ALL_QUADS (REC_QUADS + IN_QUADS)   // 425000

// ------------------------- device scratch (no allocs) -------------------------
__device__ float4        g_total[BB * NN];        // (b, n, 4 receptors) accumulated input
__device__ float         g_v[BB * NN];
__device__ float         g_r[BB * NN];
__device__ float         g_a1[BB * NN];
__device__ float         g_a2[BB * NN];
__device__ float4        g_psc_rise[BB * NN];
__device__ float4        g_psc[BB * NN];
__device__ unsigned char g_zmask[ZLEN];           // circular delay buffer, 8 batch bits/byte
__device__ unsigned char g_xmask[TT * N_INN];     // packed input spikes
__device__ float2        g_ascd[NN];              // exp(-DT * sigmoid(param_k))
__device__ int           g_zidx[E_RECN];          // precomputed d*NN + n per recurrent edge

// ------------------------------- init kernel ---------------------------------
__global__ void init_kernel(const float* __restrict__ x,
                            const float* __restrict__ bkg_w,
                            const float2* __restrict__ param_k,
                            const float* __restrict__ v0,
                            const int*   __restrict__ rec_src)
{
    int i      = blockIdx.x * blockDim.x + threadIdx.x;
    int stride = gridDim.x * blockDim.x;

    const float4* bkg4 = reinterpret_cast<const float4*>(bkg_w);
    for (int j = i; j < BB * NN; j += stride) {
        g_total[j] = bkg4[j % NN];
    }
    for (int j = i; j < BB * NN; j += stride) {
        g_v[j]  = v0[j];
        g_r[j]  = 0.0f;
        g_a1[j] = 0.0f;
        g_a2[j] = 0.0f;
        g_psc_rise[j] = make_float4(0.f, 0.f, 0.f, 0.f);
        g_psc[j]      = make_float4(0.f, 0.f, 0.f, 0.f);
    }
    for (int j = i; j < ZLEN; j += stride) g_zmask[j] = 0;
    for (int j = i; j < TT * N_INN; j += stride) {
        int t = j / N_INN;
        int s = j - t * N_INN;
        unsigned m = 0;
        #pragma unroll
        for (int b = 0; b < BB; b++) {
            if (x[(t * BB + b) * N_INN + s] > 0.5f) m |= (1u << b);
        }
        g_xmask[j] = (unsigned char)m;
    }
    for (int j = i; j < NN; j += stride) {
        float2 pk = param_k[j];
        float s0 = 1.0f / (1.0f + expf(-pk.x));
        float s1 = 1.0f / (1.0f + expf(-pk.y));
        g_ascd[j] = make_float2(expf(-s0), expf(-s1));
    }
    // precompute per-edge delay-buffer index (d*NN + n), removes div from hot loop
    for (int e = i; e < E_RECN; e += stride) {
        int src = rec_src[e];
        int d = src / NN;
        int n = src - d * NN;
        g_zidx[e] = d * NN + n;
    }
}

// ------------------------------ scatter kernel -------------------------------
// 4 edges per thread: int4 load of precomputed zidx, 4 independent mask gathers
// in flight, all-zero early-out, vector tgt/w loads only when a quad is active.
__global__ __launch_bounds__(256)
void scatter_kernel(const int*   __restrict__ rec_tgt,
                    const float* __restrict__ w_rec,
                    const int*   __restrict__ in_src,
                    const int*   __restrict__ in_tgt,
                    const float* __restrict__ w_in,
                    int h_read, int t)
{
    int q = blockIdx.x * blockDim.x + threadIdx.x;
    float* tot = reinterpret_cast<float*>(g_total);
    const int base = h_read * NN;

    if (q < REC_QUADS) {
        const int e0 = q * 4;
        int4 zi = *reinterpret_cast<const int4*>(&g_zidx[e0]);

        int i0 = zi.x + base; if (i0 >= ZLEN) i0 -= ZLEN;
        int i1 = zi.y + base; if (i1 >= ZLEN) i1 -= ZLEN;
        int i2 = zi.z + base; if (i2 >= ZLEN) i2 -= ZLEN;
        int i3 = zi.w + base; if (i3 >= ZLEN) i3 -= ZLEN;

        unsigned m0 = g_zmask[i0];
        unsigned m1 = g_zmask[i1];
        unsigned m2 = g_zmask[i2];
        unsigned m3 = g_zmask[i3];

        if ((m0 | m1 | m2 | m3) == 0u) return;

        int4   tg = *reinterpret_cast<const int4*>  (&rec_tgt[e0]);
        float4 ww = *reinterpret_cast<const float4*>(&w_rec[e0]);

        unsigned ms[4] = {m0, m1, m2, m3};
        int      tgs[4] = {tg.x, tg.y, tg.z, tg.w};
        float    wws[4] = {ww.x, ww.y, ww.z, ww.w};
        #pragma unroll
        for (int k = 0; k < 4; k++) {
            unsigned m = ms[k];
            if (!m) continue;
            float w = wws[k];
            int tgt = tgs[k];
            #pragma unroll
            for (int b = 0; b < BB; b++) {
                if (m & (1u << b)) atomicAdd(&tot[b * RNN + tgt], w);
            }
        }
    } else if (q < ALL_QUADS) {
        const int e0 = (q - REC_QUADS) * 4;
        int4 si = *reinterpret_cast<const int4*>(&in_src[e0]);
        const unsigned char* xm = &g_xmask[t * N_INN];

        unsigned m0 = xm[si.x];
        unsigned m1 = xm[si.y];
        unsigned m2 = xm[si.z];
        unsigned m3 = xm[si.w];

        if ((m0 | m1 | m2 | m3) == 0u) return;

        int4   tg = *reinterpret_cast<const int4*>  (&in_tgt[e0]);
        float4 ww = *reinterpret_cast<const float4*>(&w_in[e0]);

        unsigned ms[4] = {m0, m1, m2, m3};
        int      tgs[4] = {tg.x, tg.y, tg.z, tg.w};
        float    wws[4] = {ww.x, ww.y, ww.z, ww.w};
        #pragma unroll
        for (int k = 0; k < 4; k++) {
            unsigned m = ms[k];
            if (!m) continue;
            float w = wws[k];
            int tgt = tgs[k];
            #pragma unroll
            for (int b = 0; b < BB; b++) {
                if (m & (1u << b)) atomicAdd(&tot[b * RNN + tgt], w);
            }
        }
    }
}

// ------------------------------ update kernel --------------------------------
__global__ __launch_bounds__(256)
void update_kernel(const float*  __restrict__ decay,
                   const float*  __restrict__ current_factor,
                   const float*  __restrict__ v_th,
                   const float*  __restrict__ e_l,
                   const float*  __restrict__ v_reset,
                   const float*  __restrict__ t_ref,
                   const float2* __restrict__ asc_amps,
                   const float*  __restrict__ param_g,
                   const float4* __restrict__ syn_decay,
                   const float4* __restrict__ psc_initial,
                   const float4* __restrict__ bkg4,
                   float*        __restrict__ out,
                   int h_read, int h_write, int t)
{
    int n = blockIdx.x * blockDim.x + threadIdx.x;
    if (n >= NN) return;

    const float  dec  = decay[n];
    const float  cf   = current_factor[n];
    const float  vth  = v_th[n];
    const float  el   = e_l[n];
    const float  vre  = v_reset[n];
    const float  tref = t_ref[n];
    const float2 amps = asc_amps[n];
    const float2 ad   = g_ascd[n];
    const float  g    = param_g[n];
    const float4 sd   = syn_decay[n];
    const float4 pi   = psc_initial[n];
    const float4 bk   = bkg4[n];

    const float gel    = g * el;
    const float invden = 1.0f / (vth - el);
    const float rstamp = vre - vth;

    unsigned pm = g_zmask[h_read * NN + n];
    unsigned nm = 0;

    #pragma unroll
    for (int b = 0; b < BB; b++) {
        int bn = b * NN + n;
        float4 total = g_total[bn];
        float4 pr = g_psc_rise[bn];
        float4 pc = g_psc[bn];
        float  v  = g_v[bn];
        float  r  = g_r[bn];
        float  a1 = g_a1[bn];
        float  a2 = g_a2[bn];
        float  pz = (pm >> b) & 1u ? 1.0f : 0.0f;

        float input_cur = pc.x + pc.y + pc.z + pc.w;
        float c1   = input_cur + a1 + a2 + gel;
        float newv = dec * v + cf * c1 + pz * rstamp;
        float newr = fmaxf(r + pz * tref - 1.0f, 0.0f);
        float na1  = ad.x * a1 + pz * amps.x;
        float na2  = ad.y * a2 + pz * amps.y;

        float4 npc, npr;
        npc.x = pc.x * sd.x + sd.x * pr.x;
        npc.y = pc.y * sd.y + sd.y * pr.y;
        npc.z = pc.z * sd.z + sd.z * pr.z;
        npc.w = pc.w * sd.w + sd.w * pr.w;
        npr.x = sd.x * pr.x + pi.x * total.x;
        npr.y = sd.y * pr.y + pi.y * total.y;
        npr.z = sd.z * pr.z + pi.z * total.z;
        npr.w = sd.w * pr.w + pi.w * total.w;

        float vsc = (newv - vth) * invden;
        float z = (vsc > 0.0f) ? 1.0f : 0.0f;
        if (newr > 0.0f) z = 0.0f;
        nm |= (z != 0.0f ? 1u : 0u) << b;

        g_v[bn]  = newv;
        g_r[bn]  = newr;
        g_a1[bn] = na1;
        g_a2[bn] = na2;
        g_psc_rise[bn] = npr;
        g_psc[bn]      = npc;
        g_total[bn] = bk;

        out[(t * BB + b) * NN + n] = z;
    }
    g_zmask[h_write * NN + n] = (unsigned char)nm;
}

// --------------------------------- launcher ----------------------------------
extern "C" void kernel_launch(void* const* d_in, const int* in_sizes, int n_in,
                              void* d_out, int out_size)
{
    const float* x        = (const float*)d_in[0];
    const float* w_rec    = (const float*)d_in[1];
    const int*   rec_src  = (const int*)  d_in[2];
    const int*   rec_tgt  = (const int*)  d_in[3];
    const float* w_in     = (const float*)d_in[4];
    const int*   in_src   = (const int*)  d_in[5];
    const int*   in_tgt   = (const int*)  d_in[6];
    const float* bkg_w    = (const float*)d_in[7];
    const float* decay    = (const float*)d_in[8];
    const float* cf       = (const float*)d_in[9];
    const float* v_th     = (const float*)d_in[10];
    const float* e_l      = (const float*)d_in[11];
    const float* v_reset  = (const float*)d_in[12];
    const float* t_ref    = (const float*)d_in[13];
    const float2* asc_amps = (const float2*)d_in[14];
    const float2* param_k  = (const float2*)d_in[15];
    const float* param_g   = (const float*)d_in[16];
    const float4* syn_decay   = (const float4*)d_in[17];
    const float4* psc_initial = (const float4*)d_in[18];
    const float* v0        = (const float*)d_in[19];
    float* out = (float*)d_out;

    init_kernel<<<1024, 256>>>(x, bkg_w, param_k, v0, rec_src);

    const int scatter_blocks = (ALL_QUADS + 255) / 256;
    const int update_blocks  = (NN + 255) / 256;

    int h = 0;
    for (int t = 0; t < TT; t++) {
        int h_read  = h;
        int h_write = (h + DD - 1) % DD;
        scatter_kernel<<<scatter_blocks, 256>>>(rec_tgt, w_rec,
                                                in_src, in_tgt, w_in,
                                                h_read, t);
        update_kernel<<<update_blocks, 256>>>(decay, cf, v_th, e_l, v_reset, t_ref,
                                              asc_amps, param_g, syn_decay, psc_initial,
                                              (const float4*)bkg_w, out,
                                              h_read, h_write, t);
        h = h_write;
    }
}